// round 1
// baseline (speedup 1.0000x reference)
#include <cuda_runtime.h>
#include <cuda_bf16.h>
#include <math.h>

#define N_NODES 100000
#define N_EDGES 1600000
#define DIM     128
#define EPSF    1e-12f

// Scratch (allowed: __device__ globals, no runtime alloc)
__device__ float g_btr[(size_t)N_NODES * DIM];   // b_tan @ W_b^T + b_b
__device__ float g_str[(size_t)N_NODES * DIM];   // l2norm(s) @ W_s^T + b_s
__device__ float g_deg[N_NODES];

// ---------------------------------------------------------------------------
// Zero the output buffer (used as accumulators) and the degree array.
// ---------------------------------------------------------------------------
__global__ void zero_kernel(float4* __restrict__ out, int n4, float* __restrict__ deg) {
    int i = blockIdx.x * blockDim.x + threadIdx.x;
    int stride = gridDim.x * blockDim.x;
    float4 z = make_float4(0.f, 0.f, 0.f, 0.f);
    for (int j = i; j < n4; j += stride) out[j] = z;
    for (int j = i; j < N_NODES; j += stride) deg[j] = 0.f;
}

// ---------------------------------------------------------------------------
// Fused row-transform + GEMM:  out[r] = act( scale(in[r]) @ W^T + bias )
// MODE 0: Poincare logmap0 scale     (b pre-transform)
// MODE 1: L2-normalize scale         (s pre-transform)
// MODE 2: mean-divide by deg         (e finalize; LEAKY=true applies leaky relu)
// One warp per row. W^T staged in shared memory (k-major, float4 per lane).
// ---------------------------------------------------------------------------
template <int MODE, bool LEAKY>
__global__ void row_gemm(const float* __restrict__ in,
                         const float* __restrict__ W,
                         const float* __restrict__ bias,
                         float* __restrict__ out,
                         const float* __restrict__ deg) {
    extern __shared__ float sh[];
    float* Wt = sh;                         // [128][128], Wt[k*128+c] = W[c*128+k]
    float* xb = sh + DIM * DIM;             // [8][128] per-warp row buffers

    int tid  = threadIdx.x;
    int lane = tid & 31;
    int wrp  = tid >> 5;

    // Stage W transposed: conflict-free STS (consecutive tid -> consecutive smem)
    for (int idx = tid; idx < DIM * DIM; idx += blockDim.x) {
        int k = idx >> 7;
        int c = idx & 127;
        Wt[idx] = __ldg(W + c * DIM + k);
    }
    __syncthreads();

    const float4* Wt4 = (const float4*)Wt;
    float4 bias4 = __ldg((const float4*)bias + lane);
    float* myx = xb + wrp * DIM;

    int gw = blockIdx.x * (blockDim.x >> 5) + wrp;
    int nW = gridDim.x * (blockDim.x >> 5);

    for (int r = gw; r < N_NODES; r += nW) {
        float4 v = __ldg((const float4*)in + (size_t)r * 32 + lane);

        float s;
        if (MODE == 2) {
            float dg = __ldg(deg + r);
            s = (dg > 0.f) ? (1.f / dg) : 0.f;
        } else {
            float ss = v.x * v.x + v.y * v.y + v.z * v.z + v.w * v.w;
            #pragma unroll
            for (int o = 16; o; o >>= 1) ss += __shfl_xor_sync(0xffffffffu, ss, o);
            float n = sqrtf(ss);
            if (MODE == 0) {
                float n_safe = fmaxf(n, EPSF);
                float n_cl   = fminf(n_safe, 1.f - 1e-5f);
                s = atanhf(n_cl) / n_safe;
            } else {
                s = 1.f / fmaxf(n, EPSF);
            }
        }
        v.x *= s; v.y *= s; v.z *= s; v.w *= s;

        ((float4*)myx)[lane] = v;
        __syncwarp();

        float4 a = bias4;
        #pragma unroll 8
        for (int k = 0; k < DIM; k++) {
            float  xk = myx[k];
            float4 wv = Wt4[k * 32 + lane];
            a.x = fmaf(xk, wv.x, a.x);
            a.y = fmaf(xk, wv.y, a.y);
            a.z = fmaf(xk, wv.z, a.z);
            a.w = fmaf(xk, wv.w, a.w);
        }
        __syncwarp();   // all lanes done reading myx before next row overwrites

        if (LEAKY) {
            a.x = (a.x >= 0.f) ? a.x : 0.2f * a.x;
            a.y = (a.y >= 0.f) ? a.y : 0.2f * a.y;
            a.z = (a.z >= 0.f) ? a.z : 0.2f * a.z;
            a.w = (a.w >= 0.f) ? a.w : 0.2f * a.w;
        }
        ((float4*)out)[(size_t)r * 32 + lane] = a;
    }
}

// ---------------------------------------------------------------------------
// Edge aggregation: acc[dst] += feat[src], one warp per edge.
// Vectorized L2 reduction (red.global.add.v4.f32, sm_90+).
// ---------------------------------------------------------------------------
__global__ void agg_kernel(const float* __restrict__ feat,
                           float* __restrict__ acc,
                           const int* __restrict__ src,
                           const int* __restrict__ dst,
                           float* __restrict__ deg) {
    int lane = threadIdx.x & 31;
    int gw = (blockIdx.x * blockDim.x + threadIdx.x) >> 5;
    int nW = (gridDim.x * blockDim.x) >> 5;

    for (int e = gw; e < N_EDGES; e += nW) {
        int s = __ldg(src + e);
        int d = __ldg(dst + e);
        float4 v = __ldg((const float4*)feat + (size_t)s * 32 + lane);
        float* p = acc + (size_t)d * DIM + lane * 4;
        asm volatile("red.global.add.v4.f32 [%0], {%1, %2, %3, %4};"
                     :: "l"(p), "f"(v.x), "f"(v.y), "f"(v.z), "f"(v.w)
                     : "memory");
        if (deg != nullptr && lane == 0) atomicAdd(deg + d, 1.f);
    }
}

// ---------------------------------------------------------------------------
// Elementwise finalize, one warp per row (needs a row norm).
// MODE 0: b: v = acc/deg (0 if deg==0); out = tanh(max(|v|,EPS)) * v / max(|v|,EPS)
// MODE 1: s: v = acc/deg (0 if deg==0); out = v / max(|v|,EPS)
// ---------------------------------------------------------------------------
template <int MODE>
__global__ void finalize_vec(float* __restrict__ buf, const float* __restrict__ deg) {
    int lane = threadIdx.x & 31;
    int gw = (blockIdx.x * blockDim.x + threadIdx.x) >> 5;
    int nW = (gridDim.x * blockDim.x) >> 5;

    for (int r = gw; r < N_NODES; r += nW) {
        float dg  = __ldg(deg + r);
        float inv = (dg > 0.f) ? (1.f / dg) : 0.f;
        float4 v = ((const float4*)buf)[(size_t)r * 32 + lane];
        v.x *= inv; v.y *= inv; v.z *= inv; v.w *= inv;

        float ss = v.x * v.x + v.y * v.y + v.z * v.z + v.w * v.w;
        #pragma unroll
        for (int o = 16; o; o >>= 1) ss += __shfl_xor_sync(0xffffffffu, ss, o);
        float n  = sqrtf(ss);
        float ns = fmaxf(n, EPSF);
        float sc = (MODE == 0) ? (tanhf(ns) / ns) : (1.f / ns);

        v.x *= sc; v.y *= sc; v.z *= sc; v.w *= sc;
        ((float4*)buf)[(size_t)r * 32 + lane] = v;
    }
}

// ---------------------------------------------------------------------------
// Launch
// ---------------------------------------------------------------------------
extern "C" void kernel_launch(void* const* d_in, const int* in_sizes, int n_in,
                              void* d_out, int out_size) {
    const float* e_emb = (const float*)d_in[0];
    const float* b_emb = (const float*)d_in[1];
    const float* s_emb = (const float*)d_in[2];
    const float* W_e   = (const float*)d_in[3];
    const float* b_e   = (const float*)d_in[4];
    const float* W_b   = (const float*)d_in[5];
    const float* b_b   = (const float*)d_in[6];
    const float* W_s   = (const float*)d_in[7];
    const float* b_s   = (const float*)d_in[8];
    const int*   src   = (const int*)d_in[9];
    const int*   dst   = (const int*)d_in[10];

    float* out   = (float*)d_out;
    float* e_out = out;
    float* b_out = out + (size_t)N_NODES * DIM;
    float* s_out = out + 2 * (size_t)N_NODES * DIM;

    float *btr, *str_, *deg;
    cudaGetSymbolAddress((void**)&btr,  g_btr);
    cudaGetSymbolAddress((void**)&str_, g_str);
    cudaGetSymbolAddress((void**)&deg,  g_deg);

    const int SMEM = (DIM * DIM + 8 * DIM) * (int)sizeof(float);   // 69632 B
    cudaFuncSetAttribute(row_gemm<0, false>, cudaFuncAttributeMaxDynamicSharedMemorySize, SMEM);
    cudaFuncSetAttribute(row_gemm<1, false>, cudaFuncAttributeMaxDynamicSharedMemorySize, SMEM);
    cudaFuncSetAttribute(row_gemm<2, true>,  cudaFuncAttributeMaxDynamicSharedMemorySize, SMEM);

    // 1) zero accumulators (d_out) + deg
    zero_kernel<<<4096, 256>>>((float4*)out, 3 * N_NODES * DIM / 4, deg);

    // 2) pre-transforms + GEMMs into scratch
    row_gemm<0, false><<<444, 256, SMEM>>>(b_emb, W_b, b_b, btr,  nullptr);
    row_gemm<1, false><<<444, 256, SMEM>>>(s_emb, W_s, b_s, str_, nullptr);

    // 3) edge aggregations (one tensor at a time for L2 residency)
    agg_kernel<<<8192, 256>>>(e_emb, e_out, src, dst, deg);
    agg_kernel<<<8192, 256>>>(btr,   b_out, src, dst, nullptr);
    agg_kernel<<<8192, 256>>>(str_,  s_out, src, dst, nullptr);

    // 4) finalize
    row_gemm<2, true><<<444, 256, SMEM>>>(e_out, W_e, b_e, e_out, deg);
    finalize_vec<0><<<2048, 256>>>(b_out, deg);
    finalize_vec<1><<<2048, 256>>>(s_out, deg);
}

// round 2
// speedup vs baseline: 1.7803x; 1.7803x over previous
#include <cuda_runtime.h>
#include <cuda_bf16.h>
#include <math.h>

#define N_NODES 100000
#define N_EDGES 1600000
#define DIM     128
#define EPSF    1e-12f
#define TILE_M  64

// ---------------- scratch (__device__ globals; no runtime alloc) ------------
__device__ float g_btr [(size_t)N_NODES * DIM];
__device__ float g_str [(size_t)N_NODES * DIM];
__device__ float g_emean[(size_t)N_NODES * DIM];
__device__ float g_bscale[N_NODES];
__device__ float g_sscale[N_NODES];
__device__ int   g_counts[N_NODES];
__device__ int   g_rowptr[N_NODES + 1];
__device__ int   g_cursor[N_NODES];
__device__ int   g_csr   [N_EDGES];
__device__ float g_Wt    [3 * DIM * DIM];   // transposed W_e, W_b, W_s

// ---------------- W transpose (128x128), 32x32 smem tiles -------------------
__global__ void transpose128(const float* __restrict__ W, float* __restrict__ Wt) {
    __shared__ float t[32][33];
    int bx = blockIdx.x * 32, by = blockIdx.y * 32;
    int x = threadIdx.x, y = threadIdx.y;            // (32, 8)
    #pragma unroll
    for (int j = 0; j < 32; j += 8)
        t[y + j][x] = W[(by + y + j) * DIM + bx + x];
    __syncthreads();
    #pragma unroll
    for (int j = 0; j < 32; j += 8)
        Wt[(bx + y + j) * DIM + by + x] = t[x][y + j];
}

// ---------------- CSR build --------------------------------------------------
__global__ void hist_kernel(const int* __restrict__ dst, int* __restrict__ counts) {
    int i = blockIdx.x * blockDim.x + threadIdx.x;
    int stride = gridDim.x * blockDim.x;
    for (int e = i; e < N_EDGES; e += stride)
        atomicAdd(counts + __ldg(dst + e), 1);
}

__global__ void scan_kernel(const int* __restrict__ counts,
                            int* __restrict__ rowptr, int* __restrict__ cursor) {
    __shared__ int s[1024];
    const int T = 1024, CH = (N_NODES + T - 1) / T;  // 98
    int t = threadIdx.x;
    int lo = t * CH, hi = min(lo + CH, N_NODES);
    int sum = 0;
    for (int i = lo; i < hi; i++) sum += counts[i];
    s[t] = sum;
    __syncthreads();
    for (int off = 1; off < T; off <<= 1) {
        int v = (t >= off) ? s[t - off] : 0;
        __syncthreads();
        s[t] += v;
        __syncthreads();
    }
    int run = (t == 0) ? 0 : s[t - 1];
    for (int i = lo; i < hi; i++) {
        rowptr[i] = run; cursor[i] = run;
        run += counts[i];
    }
    if (t == T - 1) rowptr[N_NODES] = run;
}

__global__ void scatter_kernel(const int* __restrict__ src, const int* __restrict__ dst,
                               int* __restrict__ cursor, int* __restrict__ csr) {
    int i = blockIdx.x * blockDim.x + threadIdx.x;
    int stride = gridDim.x * blockDim.x;
    for (int e = i; e < N_EDGES; e += stride) {
        int d = __ldg(dst + e);
        int p = atomicAdd(cursor + d, 1);
        csr[p] = __ldg(src + e);
    }
}

// ---------------- per-row pre-scales (logmap0 / l2norm) ---------------------
__global__ void scale_kernel(const float* __restrict__ b_emb, const float* __restrict__ s_emb,
                             float* __restrict__ bscale, float* __restrict__ sscale) {
    int lane = threadIdx.x & 31;
    int gw = (blockIdx.x * blockDim.x + threadIdx.x) >> 5;
    int nW = (gridDim.x * blockDim.x) >> 5;
    for (int r = gw; r < N_NODES; r += nW) {
        float4 b = __ldg((const float4*)b_emb + (size_t)r * 32 + lane);
        float4 s = __ldg((const float4*)s_emb + (size_t)r * 32 + lane);
        float nb = b.x*b.x + b.y*b.y + b.z*b.z + b.w*b.w;
        float ns = s.x*s.x + s.y*s.y + s.z*s.z + s.w*s.w;
        #pragma unroll
        for (int o = 16; o; o >>= 1) {
            nb += __shfl_xor_sync(0xffffffffu, nb, o);
            ns += __shfl_xor_sync(0xffffffffu, ns, o);
        }
        if (lane == 0) {
            float n_safe = fmaxf(sqrtf(nb), EPSF);
            float n_cl   = fminf(n_safe, 1.f - 1e-5f);
            bscale[r] = atanhf(n_cl) / n_safe;
            sscale[r] = 1.f / fmaxf(sqrtf(ns), EPSF);
        }
    }
}

// ---------------- register-tiled GEMM: Y = act(scale(X) @ W^T + b) ----------
// MODE 0: plain (+bias)   MODE 1: row prescale (+bias)   MODE 2: leaky (+bias)
template <int MODE>
__global__ void __launch_bounds__(256, 2)
gemm128(const float* __restrict__ X, const float* __restrict__ scale,
        const float* __restrict__ Wt, const float* __restrict__ bias,
        float* __restrict__ Y) {
    extern __shared__ float sh[];
    float* Ws = sh;                  // [k][c] 128x128
    float* Xs = sh + DIM * DIM;      // [r][k] 64x128

    int tid = threadIdx.x;
    int row0 = blockIdx.x * TILE_M;

    // stage W^T (k-major, coalesced float4)
    const float4* Wt4 = (const float4*)Wt;
    float4* Ws4 = (float4*)Ws;
    #pragma unroll
    for (int i = 0; i < 16; i++) Ws4[tid + 256 * i] = __ldg(Wt4 + tid + 256 * i);

    // stage X tile (coalesced float4, optional prescale)
    const float4* X4 = (const float4*)X;
    float4* Xs4 = (float4*)Xs;
    #pragma unroll
    for (int i = 0; i < 8; i++) {
        int f = tid + 256 * i;
        int r = f >> 5, c4 = f & 31;
        int gr = row0 + r;
        float4 v = make_float4(0.f, 0.f, 0.f, 0.f);
        if (gr < N_NODES) {
            v = __ldg(X4 + (size_t)gr * 32 + c4);
            if (MODE == 1) {
                float sc = __ldg(scale + gr);
                v.x *= sc; v.y *= sc; v.z *= sc; v.w *= sc;
            }
        }
        Xs4[f] = v;
    }
    __syncthreads();

    int warp = tid >> 5, lane = tid & 31;
    int r0 = warp * 8;
    int c0 = lane * 4;

    float4 bv = __ldg((const float4*)bias + lane);
    float4 acc[8];
    #pragma unroll
    for (int i = 0; i < 8; i++) acc[i] = bv;

    #pragma unroll 4
    for (int k = 0; k < DIM; k++) {
        float4 b = *(const float4*)(Ws + k * DIM + c0);
        #pragma unroll
        for (int i = 0; i < 8; i++) {
            float a = Xs[(r0 + i) * DIM + k];
            acc[i].x = fmaf(a, b.x, acc[i].x);
            acc[i].y = fmaf(a, b.y, acc[i].y);
            acc[i].z = fmaf(a, b.z, acc[i].z);
            acc[i].w = fmaf(a, b.w, acc[i].w);
        }
    }

    #pragma unroll
    for (int i = 0; i < 8; i++) {
        int gr = row0 + r0 + i;
        if (gr < N_NODES) {
            float4 v = acc[i];
            if (MODE == 2) {
                v.x = (v.x >= 0.f) ? v.x : 0.2f * v.x;
                v.y = (v.y >= 0.f) ? v.y : 0.2f * v.y;
                v.z = (v.z >= 0.f) ? v.z : 0.2f * v.z;
                v.w = (v.w >= 0.f) ? v.w : 0.2f * v.w;
            }
            ((float4*)Y)[(size_t)gr * 32 + lane] = v;
        }
    }
}

// ---------------- CSR mean-aggregate, warp per node, fused epilogue ---------
// FIN 0: store mean   FIN 1: Poincare expmap0   FIN 2: l2 normalize
template <int FIN>
__global__ void agg_csr(const float* __restrict__ feat, float* __restrict__ out,
                        const int* __restrict__ csr, const int* __restrict__ rp) {
    int lane = threadIdx.x & 31;
    int node = (blockIdx.x * blockDim.x + threadIdx.x) >> 5;
    if (node >= N_NODES) return;

    int beg = __ldg(rp + node), end = __ldg(rp + node + 1);
    float4 acc = make_float4(0.f, 0.f, 0.f, 0.f);
    const float4* f4 = (const float4*)feat;

    for (int base = beg; base < end; base += 32) {
        int n = min(32, end - base);
        int sidx = (base + lane < end) ? __ldg(csr + base + lane) : 0;
        int j = 0;
        for (; j + 4 <= n; j += 4) {
            int s0 = __shfl_sync(0xffffffffu, sidx, j);
            int s1 = __shfl_sync(0xffffffffu, sidx, j + 1);
            int s2 = __shfl_sync(0xffffffffu, sidx, j + 2);
            int s3 = __shfl_sync(0xffffffffu, sidx, j + 3);
            float4 v0 = __ldg(f4 + (size_t)s0 * 32 + lane);
            float4 v1 = __ldg(f4 + (size_t)s1 * 32 + lane);
            float4 v2 = __ldg(f4 + (size_t)s2 * 32 + lane);
            float4 v3 = __ldg(f4 + (size_t)s3 * 32 + lane);
            acc.x += v0.x + v1.x + v2.x + v3.x;
            acc.y += v0.y + v1.y + v2.y + v3.y;
            acc.z += v0.z + v1.z + v2.z + v3.z;
            acc.w += v0.w + v1.w + v2.w + v3.w;
        }
        for (; j < n; j++) {
            int s = __shfl_sync(0xffffffffu, sidx, j);
            float4 v = __ldg(f4 + (size_t)s * 32 + lane);
            acc.x += v.x; acc.y += v.y; acc.z += v.z; acc.w += v.w;
        }
    }

    int deg = end - beg;
    float inv = (deg > 0) ? (1.f / (float)deg) : 0.f;
    acc.x *= inv; acc.y *= inv; acc.z *= inv; acc.w *= inv;

    if (FIN != 0) {
        float ss = acc.x*acc.x + acc.y*acc.y + acc.z*acc.z + acc.w*acc.w;
        #pragma unroll
        for (int o = 16; o; o >>= 1) ss += __shfl_xor_sync(0xffffffffu, ss, o);
        float ns = fmaxf(sqrtf(ss), EPSF);
        float sc = (FIN == 1) ? (tanhf(ns) / ns) : (1.f / ns);
        acc.x *= sc; acc.y *= sc; acc.z *= sc; acc.w *= sc;
    }
    ((float4*)out)[(size_t)node * 32 + lane] = acc;
}

// ---------------- launch ------------------------------------------------------
extern "C" void kernel_launch(void* const* d_in, const int* in_sizes, int n_in,
                              void* d_out, int out_size) {
    const float* e_emb = (const float*)d_in[0];
    const float* b_emb = (const float*)d_in[1];
    const float* s_emb = (const float*)d_in[2];
    const float* W_e   = (const float*)d_in[3];
    const float* b_e   = (const float*)d_in[4];
    const float* W_b   = (const float*)d_in[5];
    const float* b_b   = (const float*)d_in[6];
    const float* W_s   = (const float*)d_in[7];
    const float* b_s   = (const float*)d_in[8];
    const int*   src   = (const int*)d_in[9];
    const int*   dst   = (const int*)d_in[10];

    float* out   = (float*)d_out;
    float* e_out = out;
    float* b_out = out + (size_t)N_NODES * DIM;
    float* s_out = out + 2 * (size_t)N_NODES * DIM;

    float *btr, *str_, *emean, *bscale, *sscale, *Wt;
    int *counts, *rowptr, *cursor, *csr;
    cudaGetSymbolAddress((void**)&btr,    g_btr);
    cudaGetSymbolAddress((void**)&str_,   g_str);
    cudaGetSymbolAddress((void**)&emean,  g_emean);
    cudaGetSymbolAddress((void**)&bscale, g_bscale);
    cudaGetSymbolAddress((void**)&sscale, g_sscale);
    cudaGetSymbolAddress((void**)&counts, g_counts);
    cudaGetSymbolAddress((void**)&rowptr, g_rowptr);
    cudaGetSymbolAddress((void**)&cursor, g_cursor);
    cudaGetSymbolAddress((void**)&csr,    g_csr);
    cudaGetSymbolAddress((void**)&Wt,     g_Wt);

    const int GSMEM = (DIM * DIM + TILE_M * DIM) * (int)sizeof(float);  // 98304
    cudaFuncSetAttribute(gemm128<0>, cudaFuncAttributeMaxDynamicSharedMemorySize, GSMEM);
    cudaFuncSetAttribute(gemm128<1>, cudaFuncAttributeMaxDynamicSharedMemorySize, GSMEM);
    cudaFuncSetAttribute(gemm128<2>, cudaFuncAttributeMaxDynamicSharedMemorySize, GSMEM);

    // CSR build
    cudaMemsetAsync(counts, 0, N_NODES * sizeof(int));
    hist_kernel<<<2048, 256>>>(dst, counts);
    scan_kernel<<<1, 1024>>>(counts, rowptr, cursor);
    scatter_kernel<<<2048, 256>>>(src, dst, cursor, csr);

    // W transposes + row scales (independent of CSR)
    dim3 tb(32, 8), tg(4, 4);
    transpose128<<<tg, tb>>>(W_e, Wt + 0 * DIM * DIM);
    transpose128<<<tg, tb>>>(W_b, Wt + 1 * DIM * DIM);
    transpose128<<<tg, tb>>>(W_s, Wt + 2 * DIM * DIM);
    scale_kernel<<<1024, 256>>>(b_emb, s_emb, bscale, sscale);

    const int GGRID = (N_NODES + TILE_M - 1) / TILE_M;   // 1563
    const int AGRID = (N_NODES * 32 + 255) / 256;        // 12500

    // b path: GEMM then aggregate (+expmap0)
    gemm128<1><<<GGRID, 256, GSMEM>>>(b_emb, bscale, Wt + 1 * DIM * DIM, b_b, btr);
    agg_csr<1><<<AGRID, 256>>>(btr, b_out, csr, rowptr);

    // s path: GEMM then aggregate (+l2norm)
    gemm128<1><<<GGRID, 256, GSMEM>>>(s_emb, sscale, Wt + 2 * DIM * DIM, b_s, str_);
    agg_csr<2><<<AGRID, 256>>>(str_, s_out, csr, rowptr);

    // e path: aggregate then GEMM (+leaky)
    agg_csr<0><<<AGRID, 256>>>(e_emb, emean, csr, rowptr);
    gemm128<2><<<GGRID, 256, GSMEM>>>(emean, nullptr, Wt + 0 * DIM * DIM, b_e, e_out);
}

// round 3
// speedup vs baseline: 2.2729x; 1.2767x over previous
#include <cuda_runtime.h>
#include <cuda_fp16.h>
#include <math.h>

#define N_NODES 100000
#define N_EDGES 1600000
#define DIM     128
#define EPSF    1e-12f
#define TILE_M  64
#define NBLK    ((N_NODES + 255) / 256)   // 391

// ---------------- scratch (__device__ globals) -------------------------------
__device__ __align__(16) __half g_pack[(size_t)N_NODES * 384];  // [e|b_tan|s_nrm] fp16
__device__ float g_emean[(size_t)N_NODES * DIM];
__device__ float g_bmean[(size_t)N_NODES * DIM];
__device__ float g_smean[(size_t)N_NODES * DIM];
__device__ int   g_counts[N_NODES];
__device__ int   g_rowptr[N_NODES + 1];
__device__ int   g_cursor[N_NODES];
__device__ int   g_csr   [N_EDGES];
__device__ int   g_bsum  [NBLK];
__device__ int   g_boff  [NBLK + 1];
__device__ float g_Wt    [3 * DIM * DIM];

// ---------------- W transpose ------------------------------------------------
__global__ void transpose128(const float* __restrict__ W, float* __restrict__ Wt) {
    __shared__ float t[32][33];
    int bx = blockIdx.x * 32, by = blockIdx.y * 32;
    int x = threadIdx.x, y = threadIdx.y;            // (32, 8)
    #pragma unroll
    for (int j = 0; j < 32; j += 8)
        t[y + j][x] = W[(by + y + j) * DIM + bx + x];
    __syncthreads();
    #pragma unroll
    for (int j = 0; j < 32; j += 8)
        Wt[(bx + y + j) * DIM + by + x] = t[x][y + j];
}

// ---------------- CSR build: hist -> 3-phase scan -> scatter ------------------
__global__ void hist_kernel(const int* __restrict__ dst, int* __restrict__ counts) {
    int i = blockIdx.x * blockDim.x + threadIdx.x;
    int stride = gridDim.x * blockDim.x;
    for (int e = i; e < N_EDGES; e += stride)
        atomicAdd(counts + __ldg(dst + e), 1);
}

__global__ void block_sums(const int* __restrict__ counts, int* __restrict__ bsum) {
    int gid = blockIdx.x * 256 + threadIdx.x;
    int v = (gid < N_NODES) ? counts[gid] : 0;
    #pragma unroll
    for (int o = 16; o; o >>= 1) v += __shfl_down_sync(0xffffffffu, v, o);
    __shared__ int w[8];
    if ((threadIdx.x & 31) == 0) w[threadIdx.x >> 5] = v;
    __syncthreads();
    if (threadIdx.x == 0) {
        int s = 0;
        #pragma unroll
        for (int i = 0; i < 8; i++) s += w[i];
        bsum[blockIdx.x] = s;
    }
}

__global__ void scan_bsums(const int* __restrict__ bsum, int* __restrict__ boff) {
    __shared__ int s[512];
    int t = threadIdx.x;
    s[t] = (t < NBLK) ? bsum[t] : 0;
    __syncthreads();
    for (int o = 1; o < 512; o <<= 1) {
        int v = (t >= o) ? s[t - o] : 0;
        __syncthreads();
        s[t] += v;
        __syncthreads();
    }
    if (t == 0) boff[0] = 0;
    if (t < NBLK) boff[t + 1] = s[t];
}

__global__ void write_rowptr(const int* __restrict__ counts, const int* __restrict__ boff,
                             int* __restrict__ rowptr, int* __restrict__ cursor) {
    int b = blockIdx.x;
    int gid = b * 256 + threadIdx.x;
    int lane = threadIdx.x & 31, wid = threadIdx.x >> 5;
    int v = (gid < N_NODES) ? counts[gid] : 0;

    int x = v;  // warp inclusive scan
    #pragma unroll
    for (int o = 1; o < 32; o <<= 1) {
        int y = __shfl_up_sync(0xffffffffu, x, o);
        if (lane >= o) x += y;
    }
    __shared__ int wt[8];
    if (lane == 31) wt[wid] = x;
    __syncthreads();
    __shared__ int woff[8];
    if (threadIdx.x == 0) {
        int run = 0;
        #pragma unroll
        for (int i = 0; i < 8; i++) { woff[i] = run; run += wt[i]; }
    }
    __syncthreads();
    int ex = x - v + woff[wid] + __ldg(boff + b);
    if (gid < N_NODES) { rowptr[gid] = ex; cursor[gid] = ex; }
    if (gid == 0) rowptr[N_NODES] = __ldg(boff + NBLK);
}

__global__ void scatter_kernel(const int* __restrict__ src, const int* __restrict__ dst,
                               int* __restrict__ cursor, int* __restrict__ csr) {
    int i = blockIdx.x * blockDim.x + threadIdx.x;
    int stride = gridDim.x * blockDim.x;
    for (int e = i; e < N_EDGES; e += stride) {
        int d = __ldg(dst + e);
        int p = atomicAdd(cursor + d, 1);
        csr[p] = __ldg(src + e);
    }
}

// ---------------- pack: fp16 [N][384] = [e | logmap0(b) | l2norm(s)] ----------
__device__ __forceinline__ uint2 f4_to_h4(float4 v) {
    __half2 lo = __floats2half2_rn(v.x, v.y);
    __half2 hi = __floats2half2_rn(v.z, v.w);
    uint2 r;
    r.x = *(unsigned*)&lo;
    r.y = *(unsigned*)&hi;
    return r;
}

__global__ void pack_kernel(const float* __restrict__ e_emb, const float* __restrict__ b_emb,
                            const float* __restrict__ s_emb, __half* __restrict__ pack) {
    int lane = threadIdx.x & 31;
    int node = (blockIdx.x * blockDim.x + threadIdx.x) >> 5;
    if (node >= N_NODES) return;

    float4 e = __ldg((const float4*)e_emb + (size_t)node * 32 + lane);
    float4 b = __ldg((const float4*)b_emb + (size_t)node * 32 + lane);
    float4 s = __ldg((const float4*)s_emb + (size_t)node * 32 + lane);

    float nb = b.x*b.x + b.y*b.y + b.z*b.z + b.w*b.w;
    float ns = s.x*s.x + s.y*s.y + s.z*s.z + s.w*s.w;
    #pragma unroll
    for (int o = 16; o; o >>= 1) {
        nb += __shfl_xor_sync(0xffffffffu, nb, o);
        ns += __shfl_xor_sync(0xffffffffu, ns, o);
    }
    float bn_safe = fmaxf(sqrtf(nb), EPSF);
    float bn_cl   = fminf(bn_safe, 1.f - 1e-5f);
    float bsc = atanhf(bn_cl) / bn_safe;
    float ssc = 1.f / fmaxf(sqrtf(ns), EPSF);

    b.x *= bsc; b.y *= bsc; b.z *= bsc; b.w *= bsc;
    s.x *= ssc; s.y *= ssc; s.z *= ssc; s.w *= ssc;

    uint2* row = (uint2*)(pack + (size_t)node * 384);
    row[lane]      = f4_to_h4(e);
    row[32 + lane] = f4_to_h4(b);
    row[64 + lane] = f4_to_h4(s);
}

// ---------------- fused CSR mean-aggregate over packed fp16 -------------------
__device__ __forceinline__ void h4_acc(uint2 u, float4& a) {
    float2 lo = __half22float2(*(__half2*)&u.x);
    float2 hi = __half22float2(*(__half2*)&u.y);
    a.x += lo.x; a.y += lo.y; a.z += hi.x; a.w += hi.y;
}

__global__ void agg_fused(const __half* __restrict__ pack,
                          float* __restrict__ em, float* __restrict__ bm, float* __restrict__ sm,
                          const int* __restrict__ csr, const int* __restrict__ rp) {
    int lane = threadIdx.x & 31;
    int node = (blockIdx.x * blockDim.x + threadIdx.x) >> 5;
    if (node >= N_NODES) return;

    int beg = __ldg(rp + node), end = __ldg(rp + node + 1);
    float4 ae = make_float4(0,0,0,0), ab = make_float4(0,0,0,0), as = make_float4(0,0,0,0);
    const uint2* p2 = (const uint2*)pack;

    for (int base = beg; base < end; base += 32) {
        int n = min(32, end - base);
        int sidx = (base + lane < end) ? __ldg(csr + base + lane) : 0;
        int j = 0;
        for (; j + 2 <= n; j += 2) {
            int s0 = __shfl_sync(0xffffffffu, sidx, j);
            int s1 = __shfl_sync(0xffffffffu, sidx, j + 1);
            const uint2* r0 = p2 + (size_t)s0 * 96;
            const uint2* r1 = p2 + (size_t)s1 * 96;
            uint2 e0 = __ldg(r0 + lane),      e1 = __ldg(r1 + lane);
            uint2 b0 = __ldg(r0 + 32 + lane), b1 = __ldg(r1 + 32 + lane);
            uint2 c0 = __ldg(r0 + 64 + lane), c1 = __ldg(r1 + 64 + lane);
            h4_acc(e0, ae); h4_acc(e1, ae);
            h4_acc(b0, ab); h4_acc(b1, ab);
            h4_acc(c0, as); h4_acc(c1, as);
        }
        for (; j < n; j++) {
            int s0 = __shfl_sync(0xffffffffu, sidx, j);
            const uint2* r0 = p2 + (size_t)s0 * 96;
            h4_acc(__ldg(r0 + lane), ae);
            h4_acc(__ldg(r0 + 32 + lane), ab);
            h4_acc(__ldg(r0 + 64 + lane), as);
        }
    }

    int deg = end - beg;
    float inv = (deg > 0) ? (1.f / (float)deg) : 0.f;
    ae.x *= inv; ae.y *= inv; ae.z *= inv; ae.w *= inv;
    ab.x *= inv; ab.y *= inv; ab.z *= inv; ab.w *= inv;
    as.x *= inv; as.y *= inv; as.z *= inv; as.w *= inv;

    size_t o = (size_t)node * 32 + lane;
    ((float4*)em)[o] = ae;
    ((float4*)bm)[o] = ab;
    ((float4*)sm)[o] = as;
}

// ---------------- GEMM + fused epilogue ---------------------------------------
// MODE 0: leaky ReLU (e path; bias always kept)
// MODE 1: deg-mask + Poincare expmap0 (b path)
// MODE 2: deg-mask + l2 normalize     (s path)
template <int MODE>
__global__ void __launch_bounds__(256, 2)
gemm128(const float* __restrict__ X, const float* __restrict__ Wt,
        const float* __restrict__ bias, float* __restrict__ Y,
        const int* __restrict__ rp) {
    extern __shared__ float sh[];
    float* Ws = sh;                  // [k][c] 128x128
    float* Xs = sh + DIM * DIM;      // [r][k] 64x128

    int tid = threadIdx.x;
    int row0 = blockIdx.x * TILE_M;

    const float4* Wt4 = (const float4*)Wt;
    float4* Ws4 = (float4*)Ws;
    #pragma unroll
    for (int i = 0; i < 16; i++) Ws4[tid + 256 * i] = __ldg(Wt4 + tid + 256 * i);

    const float4* X4 = (const float4*)X;
    float4* Xs4 = (float4*)Xs;
    #pragma unroll
    for (int i = 0; i < 8; i++) {
        int f = tid + 256 * i;
        int r = f >> 5, c4 = f & 31;
        int gr = row0 + r;
        Xs4[f] = (gr < N_NODES) ? __ldg(X4 + (size_t)gr * 32 + c4)
                                : make_float4(0.f, 0.f, 0.f, 0.f);
    }
    __syncthreads();

    int warp = tid >> 5, lane = tid & 31;
    int r0 = warp * 8;
    int c0 = lane * 4;

    float4 bv = __ldg((const float4*)bias + lane);
    float4 acc[8];
    #pragma unroll
    for (int i = 0; i < 8; i++) acc[i] = bv;

    #pragma unroll 4
    for (int k = 0; k < DIM; k++) {
        float4 b = *(const float4*)(Ws + k * DIM + c0);
        #pragma unroll
        for (int i = 0; i < 8; i++) {
            float a = Xs[(r0 + i) * DIM + k];
            acc[i].x = fmaf(a, b.x, acc[i].x);
            acc[i].y = fmaf(a, b.y, acc[i].y);
            acc[i].z = fmaf(a, b.z, acc[i].z);
            acc[i].w = fmaf(a, b.w, acc[i].w);
        }
    }

    #pragma unroll
    for (int i = 0; i < 8; i++) {
        int gr = row0 + r0 + i;
        if (gr >= N_NODES) continue;
        float4 v = acc[i];
        if (MODE == 0) {
            v.x = (v.x >= 0.f) ? v.x : 0.2f * v.x;
            v.y = (v.y >= 0.f) ? v.y : 0.2f * v.y;
            v.z = (v.z >= 0.f) ? v.z : 0.2f * v.z;
            v.w = (v.w >= 0.f) ? v.w : 0.2f * v.w;
        } else {
            int deg = __ldg(rp + gr + 1) - __ldg(rp + gr);
            if (deg == 0) {
                v = make_float4(0.f, 0.f, 0.f, 0.f);
            } else {
                float ss = v.x*v.x + v.y*v.y + v.z*v.z + v.w*v.w;
                #pragma unroll
                for (int o = 16; o; o >>= 1) ss += __shfl_xor_sync(0xffffffffu, ss, o);
                float ns = fmaxf(sqrtf(ss), EPSF);
                float sc = (MODE == 1) ? (tanhf(ns) / ns) : (1.f / ns);
                v.x *= sc; v.y *= sc; v.z *= sc; v.w *= sc;
            }
        }
        ((float4*)Y)[(size_t)gr * 32 + lane] = v;
    }
}

// ---------------- launch --------------------------------------------------------
extern "C" void kernel_launch(void* const* d_in, const int* in_sizes, int n_in,
                              void* d_out, int out_size) {
    const float* e_emb = (const float*)d_in[0];
    const float* b_emb = (const float*)d_in[1];
    const float* s_emb = (const float*)d_in[2];
    const float* W_e   = (const float*)d_in[3];
    const float* b_e   = (const float*)d_in[4];
    const float* W_b   = (const float*)d_in[5];
    const float* b_b   = (const float*)d_in[6];
    const float* W_s   = (const float*)d_in[7];
    const float* b_s   = (const float*)d_in[8];
    const int*   src   = (const int*)d_in[9];
    const int*   dst   = (const int*)d_in[10];

    float* out   = (float*)d_out;
    float* e_out = out;
    float* b_out = out + (size_t)N_NODES * DIM;
    float* s_out = out + 2 * (size_t)N_NODES * DIM;

    __half* pack;
    float *emean, *bmean, *smean, *Wt;
    int *counts, *rowptr, *cursor, *csr, *bsum, *boff;
    cudaGetSymbolAddress((void**)&pack,   g_pack);
    cudaGetSymbolAddress((void**)&emean,  g_emean);
    cudaGetSymbolAddress((void**)&bmean,  g_bmean);
    cudaGetSymbolAddress((void**)&smean,  g_smean);
    cudaGetSymbolAddress((void**)&counts, g_counts);
    cudaGetSymbolAddress((void**)&rowptr, g_rowptr);
    cudaGetSymbolAddress((void**)&cursor, g_cursor);
    cudaGetSymbolAddress((void**)&csr,    g_csr);
    cudaGetSymbolAddress((void**)&bsum,   g_bsum);
    cudaGetSymbolAddress((void**)&boff,   g_boff);
    cudaGetSymbolAddress((void**)&Wt,     g_Wt);

    const int GSMEM = (DIM * DIM + TILE_M * DIM) * (int)sizeof(float);  // 98304
    cudaFuncSetAttribute(gemm128<0>, cudaFuncAttributeMaxDynamicSharedMemorySize, GSMEM);
    cudaFuncSetAttribute(gemm128<1>, cudaFuncAttributeMaxDynamicSharedMemorySize, GSMEM);
    cudaFuncSetAttribute(gemm128<2>, cudaFuncAttributeMaxDynamicSharedMemorySize, GSMEM);

    // CSR build
    cudaMemsetAsync(counts, 0, N_NODES * sizeof(int));
    hist_kernel<<<2048, 256>>>(dst, counts);
    block_sums<<<NBLK, 256>>>(counts, bsum);
    scan_bsums<<<1, 512>>>(bsum, boff);
    write_rowptr<<<NBLK, 256>>>(counts, boff, rowptr, cursor);
    scatter_kernel<<<2048, 256>>>(src, dst, cursor, csr);

    // pack + W transposes (independent of CSR)
    pack_kernel<<<(N_NODES * 32 + 255) / 256, 256>>>(e_emb, b_emb, s_emb, pack);
    dim3 tb(32, 8), tg(4, 4);
    transpose128<<<tg, tb>>>(W_e, Wt + 0 * DIM * DIM);
    transpose128<<<tg, tb>>>(W_b, Wt + 1 * DIM * DIM);
    transpose128<<<tg, tb>>>(W_s, Wt + 2 * DIM * DIM);

    // fused aggregation (all three feature spaces, one CSR pass)
    agg_fused<<<(N_NODES * 32 + 255) / 256, 256>>>(pack, emean, bmean, smean, csr, rowptr);

    // GEMMs with fused epilogues
    const int GGRID = (N_NODES + TILE_M - 1) / TILE_M;
    gemm128<0><<<GGRID, 256, GSMEM>>>(emean, Wt + 0 * DIM * DIM, b_e, e_out, rowptr);
    gemm128<1><<<GGRID, 256, GSMEM>>>(bmean, Wt + 1 * DIM * DIM, b_b, b_out, rowptr);
    gemm128<2><<<GGRID, 256, GSMEM>>>(smean, Wt + 2 * DIM * DIM, b_s, s_out, rowptr);
}

// round 4
// speedup vs baseline: 4.0467x; 1.7804x over previous
#include <cuda_runtime.h>
#include <cuda_fp16.h>
#include <mma.h>
#include <math.h>

using namespace nvcuda;

#define N_NODES 100000
#define N_EDGES 1600000
#define DIM     128
#define EPSF    1e-12f
#define NBLK    ((N_NODES + 255) / 256)   // 391
#define GTILE   128

// ---------------- scratch (__device__ globals) -------------------------------
__device__ __align__(16) __half g_pack[(size_t)N_NODES * 384];  // [e|b_tan|s_nrm] fp16
__device__ __align__(16) __half g_emean[(size_t)N_NODES * DIM];
__device__ __align__(16) __half g_bmean[(size_t)N_NODES * DIM];
__device__ __align__(16) __half g_smean[(size_t)N_NODES * DIM];
__device__ __align__(16) __half g_Wth [3 * DIM * DIM];          // W^T fp16
__device__ int   g_counts[N_NODES];
__device__ int   g_rowptr[N_NODES + 1];
__device__ int   g_cursor[N_NODES];
__device__ int   g_csr   [N_EDGES];
__device__ int   g_bsum  [NBLK];
__device__ int   g_boff  [NBLK + 1];

// ---------------- W transpose -> fp16 ----------------------------------------
__global__ void transpose128h(const float* __restrict__ W, __half* __restrict__ Wt) {
    __shared__ float t[32][33];
    int bx = blockIdx.x * 32, by = blockIdx.y * 32;
    int x = threadIdx.x, y = threadIdx.y;            // (32, 8)
    #pragma unroll
    for (int j = 0; j < 32; j += 8)
        t[y + j][x] = W[(by + y + j) * DIM + bx + x];
    __syncthreads();
    #pragma unroll
    for (int j = 0; j < 32; j += 8)
        Wt[(bx + y + j) * DIM + by + x] = __float2half(t[x][y + j]);
}

// ---------------- CSR build ----------------------------------------------------
__global__ void hist_kernel(const int* __restrict__ dst, int* __restrict__ counts) {
    int i = blockIdx.x * blockDim.x + threadIdx.x;
    int stride = gridDim.x * blockDim.x;
    for (int e = i; e < N_EDGES; e += stride)
        atomicAdd(counts + __ldg(dst + e), 1);
}

__global__ void block_sums(const int* __restrict__ counts, int* __restrict__ bsum) {
    int gid = blockIdx.x * 256 + threadIdx.x;
    int v = (gid < N_NODES) ? counts[gid] : 0;
    #pragma unroll
    for (int o = 16; o; o >>= 1) v += __shfl_down_sync(0xffffffffu, v, o);
    __shared__ int w[8];
    if ((threadIdx.x & 31) == 0) w[threadIdx.x >> 5] = v;
    __syncthreads();
    if (threadIdx.x == 0) {
        int s = 0;
        #pragma unroll
        for (int i = 0; i < 8; i++) s += w[i];
        bsum[blockIdx.x] = s;
    }
}

__global__ void scan_bsums(const int* __restrict__ bsum, int* __restrict__ boff) {
    __shared__ int s[512];
    int t = threadIdx.x;
    s[t] = (t < NBLK) ? bsum[t] : 0;
    __syncthreads();
    for (int o = 1; o < 512; o <<= 1) {
        int v = (t >= o) ? s[t - o] : 0;
        __syncthreads();
        s[t] += v;
        __syncthreads();
    }
    if (t == 0) boff[0] = 0;
    if (t < NBLK) boff[t + 1] = s[t];
}

__global__ void write_rowptr(const int* __restrict__ counts, const int* __restrict__ boff,
                             int* __restrict__ rowptr, int* __restrict__ cursor) {
    int b = blockIdx.x;
    int gid = b * 256 + threadIdx.x;
    int lane = threadIdx.x & 31, wid = threadIdx.x >> 5;
    int v = (gid < N_NODES) ? counts[gid] : 0;

    int x = v;
    #pragma unroll
    for (int o = 1; o < 32; o <<= 1) {
        int y = __shfl_up_sync(0xffffffffu, x, o);
        if (lane >= o) x += y;
    }
    __shared__ int wt[8];
    if (lane == 31) wt[wid] = x;
    __syncthreads();
    __shared__ int woff[8];
    if (threadIdx.x == 0) {
        int run = 0;
        #pragma unroll
        for (int i = 0; i < 8; i++) { woff[i] = run; run += wt[i]; }
    }
    __syncthreads();
    int ex = x - v + woff[wid] + __ldg(boff + b);
    if (gid < N_NODES) { rowptr[gid] = ex; cursor[gid] = ex; }
    if (gid == 0) rowptr[N_NODES] = __ldg(boff + NBLK);
}

__global__ void scatter_kernel(const int* __restrict__ src, const int* __restrict__ dst,
                               int* __restrict__ cursor, int* __restrict__ csr) {
    int i = blockIdx.x * blockDim.x + threadIdx.x;
    int stride = gridDim.x * blockDim.x;
    for (int e = i; e < N_EDGES; e += stride) {
        int d = __ldg(dst + e);
        int p = atomicAdd(cursor + d, 1);
        csr[p] = __ldg(src + e);
    }
}

// ---------------- pack: fp16 [N][384] = [e | logmap0(b) | l2norm(s)] ----------
__device__ __forceinline__ uint2 f4_to_h4(float4 v) {
    __half2 lo = __floats2half2_rn(v.x, v.y);
    __half2 hi = __floats2half2_rn(v.z, v.w);
    uint2 r;
    r.x = *(unsigned*)&lo;
    r.y = *(unsigned*)&hi;
    return r;
}

__global__ void pack_kernel(const float* __restrict__ e_emb, const float* __restrict__ b_emb,
                            const float* __restrict__ s_emb, __half* __restrict__ pack) {
    int lane = threadIdx.x & 31;
    int node = (blockIdx.x * blockDim.x + threadIdx.x) >> 5;
    if (node >= N_NODES) return;

    float4 e = __ldg((const float4*)e_emb + (size_t)node * 32 + lane);
    float4 b = __ldg((const float4*)b_emb + (size_t)node * 32 + lane);
    float4 s = __ldg((const float4*)s_emb + (size_t)node * 32 + lane);

    float nb = b.x*b.x + b.y*b.y + b.z*b.z + b.w*b.w;
    float ns = s.x*s.x + s.y*s.y + s.z*s.z + s.w*s.w;
    #pragma unroll
    for (int o = 16; o; o >>= 1) {
        nb += __shfl_xor_sync(0xffffffffu, nb, o);
        ns += __shfl_xor_sync(0xffffffffu, ns, o);
    }
    float bn_safe = fmaxf(sqrtf(nb), EPSF);
    float bn_cl   = fminf(bn_safe, 1.f - 1e-5f);
    float bsc = atanhf(bn_cl) / bn_safe;
    float ssc = 1.f / fmaxf(sqrtf(ns), EPSF);

    b.x *= bsc; b.y *= bsc; b.z *= bsc; b.w *= bsc;
    s.x *= ssc; s.y *= ssc; s.z *= ssc; s.w *= ssc;

    uint2* row = (uint2*)(pack + (size_t)node * 384);
    row[lane]      = f4_to_h4(e);
    row[32 + lane] = f4_to_h4(b);
    row[64 + lane] = f4_to_h4(s);
}

// ---------------- fused CSR mean-aggregate (fp16 out) --------------------------
__device__ __forceinline__ void h4_acc(uint2 u, float4& a) {
    float2 lo = __half22float2(*(__half2*)&u.x);
    float2 hi = __half22float2(*(__half2*)&u.y);
    a.x += lo.x; a.y += lo.y; a.z += hi.x; a.w += hi.y;
}

__global__ void agg_fused(const __half* __restrict__ pack,
                          __half* __restrict__ em, __half* __restrict__ bm, __half* __restrict__ sm,
                          const int* __restrict__ csr, const int* __restrict__ rp) {
    int lane = threadIdx.x & 31;
    int node = (blockIdx.x * blockDim.x + threadIdx.x) >> 5;
    if (node >= N_NODES) return;

    int beg = __ldg(rp + node), end = __ldg(rp + node + 1);
    float4 ae = make_float4(0,0,0,0), ab = make_float4(0,0,0,0), as = make_float4(0,0,0,0);
    const uint2* p2 = (const uint2*)pack;

    for (int base = beg; base < end; base += 32) {
        int n = min(32, end - base);
        int sidx = (base + lane < end) ? __ldg(csr + base + lane) : 0;
        int j = 0;
        for (; j + 2 <= n; j += 2) {
            int s0 = __shfl_sync(0xffffffffu, sidx, j);
            int s1 = __shfl_sync(0xffffffffu, sidx, j + 1);
            const uint2* r0 = p2 + (size_t)s0 * 96;
            const uint2* r1 = p2 + (size_t)s1 * 96;
            uint2 e0 = __ldg(r0 + lane),      e1 = __ldg(r1 + lane);
            uint2 b0 = __ldg(r0 + 32 + lane), b1 = __ldg(r1 + 32 + lane);
            uint2 c0 = __ldg(r0 + 64 + lane), c1 = __ldg(r1 + 64 + lane);
            h4_acc(e0, ae); h4_acc(e1, ae);
            h4_acc(b0, ab); h4_acc(b1, ab);
            h4_acc(c0, as); h4_acc(c1, as);
        }
        for (; j < n; j++) {
            int s0 = __shfl_sync(0xffffffffu, sidx, j);
            const uint2* r0 = p2 + (size_t)s0 * 96;
            h4_acc(__ldg(r0 + lane), ae);
            h4_acc(__ldg(r0 + 32 + lane), ab);
            h4_acc(__ldg(r0 + 64 + lane), as);
        }
    }

    int deg = end - beg;
    float inv = (deg > 0) ? (1.f / (float)deg) : 0.f;
    ae.x *= inv; ae.y *= inv; ae.z *= inv; ae.w *= inv;
    ab.x *= inv; ab.y *= inv; ab.z *= inv; ab.w *= inv;
    as.x *= inv; as.y *= inv; as.z *= inv; as.w *= inv;

    size_t o = (size_t)node * 32 + lane;
    ((uint2*)em)[o] = f4_to_h4(ae);
    ((uint2*)bm)[o] = f4_to_h4(ab);
    ((uint2*)sm)[o] = f4_to_h4(as);
}

// ---------------- WMMA GEMM (fp16 in, fp32 acc) + fused epilogue ---------------
// Y[128-tile] = epilogue( X @ W^T + bias )
// MODE 0: leaky ReLU   MODE 1: deg-mask + expmap0   MODE 2: deg-mask + l2norm
#define LDH 136   // fp16 smem leading dim (pad 8)

template <int MODE>
__global__ void __launch_bounds__(256, 1)
gemm_wmma(const __half* __restrict__ X, const __half* __restrict__ Wt,
          const float* __restrict__ bias, float* __restrict__ Y,
          const int* __restrict__ rp) {
    extern __shared__ char sh[];
    __half* Xs = (__half*)sh;                       // [128][136]
    __half* Ws = (__half*)(sh + GTILE * LDH * 2);   // [128][136]
    float*  Os = (float*)sh;                        // [128][128] (aliases Xs/Ws)

    int tid = threadIdx.x;
    int warp = tid >> 5, lane = tid & 31;
    int row0 = blockIdx.x * GTILE;

    // stage X tile (uint2 = 4 halves per thread-iter, coalesced)
    const uint2* X2 = (const uint2*)X;
    #pragma unroll
    for (int i = 0; i < 16; i++) {
        int f = tid + 256 * i;                      // 4096 uint2 = 128x128 halves
        int r = f >> 5, c4 = f & 31;
        int gr = row0 + r;
        uint2 v = make_uint2(0u, 0u);
        if (gr < N_NODES) v = __ldg(X2 + (size_t)gr * 32 + c4);
        *(uint2*)(Xs + r * LDH + c4 * 4) = v;
    }
    // stage W^T (k-major [k][n])
    const uint2* W2 = (const uint2*)Wt;
    #pragma unroll
    for (int i = 0; i < 16; i++) {
        int f = tid + 256 * i;
        int r = f >> 5, c4 = f & 31;
        *(uint2*)(Ws + r * LDH + c4 * 4) = __ldg(W2 + f);
    }
    __syncthreads();

    // compute: warp owns rows [warp*16, +16), all 128 cols
    wmma::fragment<wmma::accumulator, 16, 16, 16, float> acc[8];
    #pragma unroll
    for (int n = 0; n < 8; n++) wmma::fill_fragment(acc[n], 0.f);

    #pragma unroll
    for (int k = 0; k < 8; k++) {
        wmma::fragment<wmma::matrix_a, 16, 16, 16, __half, wmma::row_major> a;
        wmma::load_matrix_sync(a, Xs + (warp * 16) * LDH + k * 16, LDH);
        #pragma unroll
        for (int n = 0; n < 8; n++) {
            wmma::fragment<wmma::matrix_b, 16, 16, 16, __half, wmma::row_major> b;
            wmma::load_matrix_sync(b, Ws + (k * 16) * LDH + n * 16, LDH);
            wmma::mma_sync(acc[n], a, b, acc[n]);
        }
    }
    __syncthreads();   // done reading Xs/Ws; safe to alias with Os

    #pragma unroll
    for (int n = 0; n < 8; n++)
        wmma::store_matrix_sync(Os + (warp * 16) * GTILE + n * 16, acc[n], GTILE,
                                wmma::mem_row_major);
    __syncthreads();

    // epilogue: warp per row (16 rows per warp)
    float4 bv = __ldg((const float4*)bias + lane);
    #pragma unroll
    for (int i = 0; i < 16; i++) {
        int r = warp * 16 + i;
        int gr = row0 + r;
        if (gr >= N_NODES) break;
        float4 v = *(const float4*)(Os + r * GTILE + lane * 4);
        v.x += bv.x; v.y += bv.y; v.z += bv.z; v.w += bv.w;
        if (MODE == 0) {
            v.x = (v.x >= 0.f) ? v.x : 0.2f * v.x;
            v.y = (v.y >= 0.f) ? v.y : 0.2f * v.y;
            v.z = (v.z >= 0.f) ? v.z : 0.2f * v.z;
            v.w = (v.w >= 0.f) ? v.w : 0.2f * v.w;
        } else {
            int deg = __ldg(rp + gr + 1) - __ldg(rp + gr);
            if (deg == 0) {
                v = make_float4(0.f, 0.f, 0.f, 0.f);
            } else {
                float ss = v.x*v.x + v.y*v.y + v.z*v.z + v.w*v.w;
                #pragma unroll
                for (int o = 16; o; o >>= 1) ss += __shfl_xor_sync(0xffffffffu, ss, o);
                float ns = fmaxf(sqrtf(ss), EPSF);
                float sc = (MODE == 1) ? (tanhf(ns) / ns) : (1.f / ns);
                v.x *= sc; v.y *= sc; v.z *= sc; v.w *= sc;
            }
        }
        ((float4*)Y)[(size_t)gr * 32 + lane] = v;
    }
}

// ---------------- launch --------------------------------------------------------
extern "C" void kernel_launch(void* const* d_in, const int* in_sizes, int n_in,
                              void* d_out, int out_size) {
    const float* e_emb = (const float*)d_in[0];
    const float* b_emb = (const float*)d_in[1];
    const float* s_emb = (const float*)d_in[2];
    const float* W_e   = (const float*)d_in[3];
    const float* b_e   = (const float*)d_in[4];
    const float* W_b   = (const float*)d_in[5];
    const float* b_b   = (const float*)d_in[6];
    const float* W_s   = (const float*)d_in[7];
    const float* b_s   = (const float*)d_in[8];
    const int*   src   = (const int*)d_in[9];
    const int*   dst   = (const int*)d_in[10];

    float* out   = (float*)d_out;
    float* e_out = out;
    float* b_out = out + (size_t)N_NODES * DIM;
    float* s_out = out + 2 * (size_t)N_NODES * DIM;

    __half *pack, *emean, *bmean, *smean, *Wth;
    int *counts, *rowptr, *cursor, *csr, *bsum, *boff;
    cudaGetSymbolAddress((void**)&pack,   g_pack);
    cudaGetSymbolAddress((void**)&emean,  g_emean);
    cudaGetSymbolAddress((void**)&bmean,  g_bmean);
    cudaGetSymbolAddress((void**)&smean,  g_smean);
    cudaGetSymbolAddress((void**)&Wth,    g_Wth);
    cudaGetSymbolAddress((void**)&counts, g_counts);
    cudaGetSymbolAddress((void**)&rowptr, g_rowptr);
    cudaGetSymbolAddress((void**)&cursor, g_cursor);
    cudaGetSymbolAddress((void**)&csr,    g_csr);
    cudaGetSymbolAddress((void**)&bsum,   g_bsum);
    cudaGetSymbolAddress((void**)&boff,   g_boff);

    const int GSMEM = 2 * GTILE * LDH * 2;   // 69632 B (Os aliases within)
    cudaFuncSetAttribute(gemm_wmma<0>, cudaFuncAttributeMaxDynamicSharedMemorySize, GSMEM);
    cudaFuncSetAttribute(gemm_wmma<1>, cudaFuncAttributeMaxDynamicSharedMemorySize, GSMEM);
    cudaFuncSetAttribute(gemm_wmma<2>, cudaFuncAttributeMaxDynamicSharedMemorySize, GSMEM);

    // CSR build
    cudaMemsetAsync(counts, 0, N_NODES * sizeof(int));
    hist_kernel<<<2048, 256>>>(dst, counts);
    block_sums<<<NBLK, 256>>>(counts, bsum);
    scan_bsums<<<1, 512>>>(bsum, boff);
    write_rowptr<<<NBLK, 256>>>(counts, boff, rowptr, cursor);
    scatter_kernel<<<2048, 256>>>(src, dst, cursor, csr);

    // pack + W transposes
    pack_kernel<<<(N_NODES * 32 + 255) / 256, 256>>>(e_emb, b_emb, s_emb, pack);
    dim3 tb(32, 8), tg(4, 4);
    transpose128h<<<tg, tb>>>(W_e, Wth + 0 * DIM * DIM);
    transpose128h<<<tg, tb>>>(W_b, Wth + 1 * DIM * DIM);
    transpose128h<<<tg, tb>>>(W_s, Wth + 2 * DIM * DIM);

    // fused aggregation
    agg_fused<<<(N_NODES * 32 + 255) / 256, 256>>>(pack, emean, bmean, smean, csr, rowptr);

    // tensor-core GEMMs with fused epilogues
    const int GGRID = (N_NODES + GTILE - 1) / GTILE;   // 782
    gemm_wmma<0><<<GGRID, 256, GSMEM>>>(emean, Wth + 0 * DIM * DIM, b_e, e_out, rowptr);
    gemm_wmma<1><<<GGRID, 256, GSMEM>>>(bmean, Wth + 1 * DIM * DIM, b_b, b_out, rowptr);
    gemm_wmma<2><<<GGRID, 256, GSMEM>>>(smean, Wth + 2 * DIM * DIM, b_s, s_out, rowptr);
}